// round 16
// baseline (speedup 1.0000x reference)
#include <cuda_runtime.h>
#include <cuda_bf16.h>
#include <math.h>
#include <stdint.h>

// ---------------- problem constants ----------------
#define NB    4
#define NL    1024
#define HID   2048
#define NH    16
#define DK    128
#define DV    128
#define KEYD  2048          // H*DK
#define VALD  2048          // H*DV
#define CONVD 6144          // 2*KEYD + VALD
#define QKVZN 8192          // 2*KEYD + 2*VALD
#define ML    4096          // B*L

typedef unsigned long long ull;

// ---------------- device scratch (static, no allocs) ----------------
__device__ float g_qkvz[(size_t)ML * QKVZN];   // 128 MiB
__device__ float g_x[(size_t)ML * CONVD];
__device__ float g_g[ML * NH];                 // holds exp(g)
__device__ float g_beta[ML * NH];
__device__ float g_o[(size_t)ML * VALD];

// bf16 hi/lo split operands
__device__ __nv_bfloat16 g_hh[(size_t)ML * HID];
__device__ __nv_bfloat16 g_hl[(size_t)ML * HID];
__device__ __nv_bfloat16 g_wqh[(size_t)QKVZN * HID];   // W_qkvz^T  [N,K]
__device__ __nv_bfloat16 g_wql[(size_t)QKVZN * HID];
__device__ __nv_bfloat16 g_woh[(size_t)HID * VALD];    // W_out^T   [N,K]
__device__ __nv_bfloat16 g_wol[(size_t)HID * VALD];
__device__ __nv_bfloat16 g_oh[(size_t)ML * VALD];
__device__ __nv_bfloat16 g_ol[(size_t)ML * VALD];

// ==================== PTX helpers (base compute_103 safe) ====================
__device__ __forceinline__ uint32_t smem_u32(const void* p) {
    uint32_t a;
    asm("{ .reg .u64 t; cvta.to.shared.u64 t, %1; cvt.u32.u64 %0, t; }" : "=r"(a) : "l"(p));
    return a;
}
__device__ __forceinline__ void cp16(uint32_t dst, const void* src) {
    asm volatile("cp.async.cg.shared.global [%0], [%1], 16;" :: "r"(dst), "l"(src));
}
__device__ __forceinline__ void cp4(uint32_t dst, const void* src) {
    asm volatile("cp.async.ca.shared.global [%0], [%1], 4;" :: "r"(dst), "l"(src));
}
__device__ __forceinline__ void cp_commit() {
    asm volatile("cp.async.commit_group;" ::: "memory");
}
template<int N>
__device__ __forceinline__ void cp_wait() {
    asm volatile("cp.async.wait_group %0;" :: "n"(N) : "memory");
}
__device__ __forceinline__ void bar_named(int id) {
    asm volatile("bar.sync %0, 256;" :: "r"(id) : "memory");
}
__device__ __forceinline__ void ldsm4(uint32_t* r, uint32_t addr) {
    asm volatile("ldmatrix.sync.aligned.m8n8.x4.shared.b16 {%0,%1,%2,%3}, [%4];"
                 : "=r"(r[0]), "=r"(r[1]), "=r"(r[2]), "=r"(r[3]) : "r"(addr));
}
__device__ __forceinline__ void mma16816(float* c, const uint32_t* a, const uint32_t* b) {
    asm volatile("mma.sync.aligned.m16n8k16.row.col.f32.bf16.bf16.f32 "
                 "{%0,%1,%2,%3}, {%4,%5,%6,%7}, {%8,%9}, {%0,%1,%2,%3};"
                 : "+f"(c[0]), "+f"(c[1]), "+f"(c[2]), "+f"(c[3])
                 : "r"(a[0]), "r"(a[1]), "r"(a[2]), "r"(a[3]), "r"(b[0]), "r"(b[1]));
}
__device__ __forceinline__ uint32_t sw128(uint32_t off) {
    return off ^ ((off >> 3) & 0x70);
}
// packed f32x2 (sm_100+ base ISA)
__device__ __forceinline__ ull pack2(float x, float y) {
    ull r; asm("mov.b64 %0, {%1, %2};" : "=l"(r) : "f"(x), "f"(y)); return r;
}
__device__ __forceinline__ float2 unpack2(ull v) {
    float2 f; asm("mov.b64 {%0, %1}, %2;" : "=f"(f.x), "=f"(f.y) : "l"(v)); return f;
}
__device__ __forceinline__ ull fma2(ull a, ull b, ull c) {
    ull d; asm("fma.rn.f32x2 %0, %1, %2, %3;" : "=l"(d) : "l"(a), "l"(b), "l"(c)); return d;
}
__device__ __forceinline__ ull mul2(ull a, ull b) {
    ull d; asm("mul.rn.f32x2 %0, %1, %2;" : "=l"(d) : "l"(a), "l"(b)); return d;
}
__device__ __forceinline__ ull add2(ull a, ull b) {
    ull d; asm("add.rn.f32x2 %0, %1, %2;" : "=l"(d) : "l"(a), "l"(b)); return d;
}

// ==================== mma.sync bf16 GEMM (3-product hi/lo split) =============
#define BM 128
#define BN 64
#define BKC 64
#define A_TILE_B 16384                    // 128x64 bf16
#define B_TILE_B 8192                     // 64x64 bf16
#define STAGE_B (2 * A_TILE_B + 2 * B_TILE_B)   // 48 KiB
#define GEMM_SMEM (2 * STAGE_B)                 // 96 KiB

__device__ __forceinline__ void gemm_load_chunk(
    const __nv_bfloat16* Ah, const __nv_bfloat16* Al,
    const __nv_bfloat16* Bh, const __nv_bfloat16* Bl,
    int Kdim, int k0, uint32_t sbuf, int tid)
{
#pragma unroll
    for (int it = 0; it < 4; it++) {          // A: 128 rows x 8 x16B
        const int u   = it * 256 + tid;
        const int row = u >> 3;
        const int cb  = (u & 7) << 4;
        const uint32_t so = sw128((uint32_t)(row * 128 + cb));
        const size_t go = (size_t)row * Kdim + k0;
        cp16(sbuf + 0 * A_TILE_B + so, (const char*)(Ah + go) + cb);
        cp16(sbuf + 1 * A_TILE_B + so, (const char*)(Al + go) + cb);
    }
#pragma unroll
    for (int it = 0; it < 2; it++) {          // B: 64 rows x 8 x16B
        const int u   = it * 256 + tid;
        const int row = u >> 3;
        const int cb  = (u & 7) << 4;
        const uint32_t so = sw128((uint32_t)(row * 128 + cb));
        const size_t go = (size_t)row * Kdim + k0;
        cp16(sbuf + 2 * A_TILE_B + so,             (const char*)(Bh + go) + cb);
        cp16(sbuf + 2 * A_TILE_B + B_TILE_B + so,  (const char*)(Bl + go) + cb);
    }
}

__global__ void __launch_bounds__(256, 2) mma_gemm(
    const __nv_bfloat16* __restrict__ Ah, const __nv_bfloat16* __restrict__ Al,
    const __nv_bfloat16* __restrict__ Bh, const __nv_bfloat16* __restrict__ Bl,
    float* __restrict__ C, int Kdim, int Nout)
{
    extern __shared__ __align__(1024) char smem[];
    const uint32_t sbase = smem_u32(smem);
    const int tid  = threadIdx.x;
    const int wid  = tid >> 5;
    const int lane = tid & 31;
    const int wm = wid >> 2;          // 0..1
    const int wn = wid & 3;           // 0..3
    const int m0 = blockIdx.y * BM;
    const int n0 = blockIdx.x * BN;

    const __nv_bfloat16* Ahb = Ah + (size_t)m0 * Kdim;
    const __nv_bfloat16* Alb = Al + (size_t)m0 * Kdim;
    const __nv_bfloat16* Bhb = Bh + (size_t)n0 * Kdim;
    const __nv_bfloat16* Blb = Bl + (size_t)n0 * Kdim;

    float acc[4][2][4];
#pragma unroll
    for (int i = 0; i < 4; i++)
#pragma unroll
        for (int j = 0; j < 2; j++)
#pragma unroll
            for (int r = 0; r < 4; r++) acc[i][j][r] = 0.f;

    const uint32_t a_off0 = (uint32_t)((wm * 64 + (lane & 15)) * 128 + ((lane >> 4) << 4));
    const uint32_t b_off0 = (uint32_t)((wn * 16 + (lane & 7) + ((lane >> 4) << 3)) * 128
                                       + (((lane >> 3) & 1) << 4));

    gemm_load_chunk(Ahb, Alb, Bhb, Blb, Kdim, 0, sbase, tid);
    cp_commit();

    const int nchunks = Kdim / BKC;
    for (int c = 0; c < nchunks; c++) {
        const uint32_t buf = sbase + (uint32_t)(c & 1) * STAGE_B;
        cp_wait<0>();
        __syncthreads();
        if (c + 1 < nchunks) {
            gemm_load_chunk(Ahb, Alb, Bhb, Blb, Kdim, (c + 1) * BKC,
                            sbase + (uint32_t)((c + 1) & 1) * STAGE_B, tid);
            cp_commit();
        }

        const uint32_t aHi = buf, aLo = buf + A_TILE_B;
        const uint32_t bHi = buf + 2 * A_TILE_B, bLo = bHi + B_TILE_B;
#pragma unroll
        for (int k16 = 0; k16 < 4; k16++) {
            uint32_t ah[4][4], al[4][4], bh[4], bl[4];
#pragma unroll
            for (int mt = 0; mt < 4; mt++) {
                const uint32_t off = sw128(a_off0 + (uint32_t)(mt * 16 * 128 + k16 * 32));
                ldsm4(ah[mt], aHi + off);
                ldsm4(al[mt], aLo + off);
            }
            {
                const uint32_t off = sw128(b_off0 + (uint32_t)(k16 * 32));
                ldsm4(bh, bHi + off);
                ldsm4(bl, bLo + off);
            }
#pragma unroll
            for (int mt = 0; mt < 4; mt++) {
#pragma unroll
                for (int nt = 0; nt < 2; nt++) {
                    const uint32_t* bhp = &bh[nt * 2];
                    const uint32_t* blp = &bl[nt * 2];
                    mma16816(acc[mt][nt], ah[mt], bhp);
                    mma16816(acc[mt][nt], ah[mt], blp);
                    mma16816(acc[mt][nt], al[mt], bhp);
                }
            }
        }
        __syncthreads();
    }

    const int rbase = m0 + wm * 64 + (lane >> 2);
    const int cbase = n0 + wn * 16 + (lane & 3) * 2;
#pragma unroll
    for (int mt = 0; mt < 4; mt++) {
#pragma unroll
        for (int nt = 0; nt < 2; nt++) {
            float* p0 = C + (size_t)(rbase + mt * 16) * Nout + cbase + nt * 8;
            float* p1 = p0 + 8 * Nout;
            *(float2*)p0 = make_float2(acc[mt][nt][0], acc[mt][nt][1]);
            *(float2*)p1 = make_float2(acc[mt][nt][2], acc[mt][nt][3]);
        }
    }
}

// ==================== fp32 -> bf16 hi/lo split ====================
__global__ void __launch_bounds__(256) split_kernel(const float* __restrict__ s,
                                                    __nv_bfloat16* __restrict__ hi,
                                                    __nv_bfloat16* __restrict__ lo,
                                                    int n4)
{
    const int i = blockIdx.x * 256 + threadIdx.x;
    if (i >= n4) return;
    float4 v = ((const float4*)s)[i];
    __nv_bfloat16 h0 = __float2bfloat16_rn(v.x);
    __nv_bfloat16 h1 = __float2bfloat16_rn(v.y);
    __nv_bfloat16 h2 = __float2bfloat16_rn(v.z);
    __nv_bfloat16 h3 = __float2bfloat16_rn(v.w);
    __nv_bfloat16 l0 = __float2bfloat16_rn(v.x - __bfloat162float(h0));
    __nv_bfloat16 l1 = __float2bfloat16_rn(v.y - __bfloat162float(h1));
    __nv_bfloat16 l2 = __float2bfloat16_rn(v.z - __bfloat162float(h2));
    __nv_bfloat16 l3 = __float2bfloat16_rn(v.w - __bfloat162float(h3));
    __nv_bfloat162* hp = (__nv_bfloat162*)(hi + (size_t)i * 4);
    __nv_bfloat162* lp = (__nv_bfloat162*)(lo + (size_t)i * 4);
    hp[0] = __nv_bfloat162(h0, h1); hp[1] = __nv_bfloat162(h2, h3);
    lp[0] = __nv_bfloat162(l0, l1); lp[1] = __nv_bfloat162(l2, l3);
}

// transpose + split: src[K,N] f32 -> hi/lo [N,K] bf16
__global__ void __launch_bounds__(256) tsplit_kernel(const float* __restrict__ src,
                                                     __nv_bfloat16* __restrict__ hi,
                                                     __nv_bfloat16* __restrict__ lo,
                                                     int K, int N)
{
    __shared__ float t[32][33];
    const int n0 = blockIdx.x * 32;
    const int k0 = blockIdx.y * 32;
    for (int j = threadIdx.y; j < 32; j += 8)
        t[j][threadIdx.x] = src[(size_t)(k0 + j) * N + n0 + threadIdx.x];
    __syncthreads();
    for (int j = threadIdx.y; j < 32; j += 8) {
        const float x = t[threadIdx.x][j];
        const __nv_bfloat16 h = __float2bfloat16_rn(x);
        const size_t oi = (size_t)(n0 + j) * K + k0 + threadIdx.x;
        hi[oi] = h;
        lo[oi] = __float2bfloat16_rn(x - __bfloat162float(h));
    }
}

// ======== small GEMM: ba[4096,32] + fused exp(g)/beta (R12 warp-per-row) =====
__global__ void __launch_bounds__(256) ba_gb_kernel(const float* __restrict__ A,
                                                    const float* __restrict__ Bm,
                                                    const float* __restrict__ A_log,
                                                    const float* __restrict__ dt_bias,
                                                    float* __restrict__ eg_out,
                                                    float* __restrict__ beta_out)
{
    const int row  = blockIdx.x * 8 + (threadIdx.x >> 5);
    const int lane = threadIdx.x & 31;
    const float* a = A + (size_t)row * HID;
    float acc = 0.f;
#pragma unroll 4
    for (int k = 0; k < HID; k += 4) {
        float4 av = *(const float4*)&a[k];
        acc += av.x * Bm[(k + 0) * 32 + lane];
        acc += av.y * Bm[(k + 1) * 32 + lane];
        acc += av.z * Bm[(k + 2) * 32 + lane];
        acc += av.w * Bm[(k + 3) * 32 + lane];
    }
    const float other = __shfl_xor_sync(0xffffffffu, acc, 16);
    if (lane < 16) {
        const int h = lane;
        const float s = other + dt_bias[h];
        const float sp = (s > 20.f) ? s : log1pf(expf(s));
        eg_out[row * NH + h]   = expf(-expf(A_log[h]) * sp);
        beta_out[row * NH + h] = 1.f / (1.f + expf(-acc));
    }
}

// ============ conv1d (rolling window, 1 warp per 128-col chunk) + l2norm =====
#define CONV_LSPLIT 16
#define CONV_SEG (NL / CONV_LSPLIT)          // 64
#define CONV_WARPS (NB * 48 * CONV_LSPLIT)   // 3072 warps
#define CONV_BLOCKS (CONV_WARPS / 8)         // 384

__global__ void __launch_bounds__(256) conv_kernel(const float* __restrict__ qkvz,
                                                   const float* __restrict__ conv_w,
                                                   const float* __restrict__ conv_b,
                                                   float* __restrict__ x_out)
{
    const int gw   = blockIdx.x * 8 + (threadIdx.x >> 5);
    const int lane = threadIdx.x & 31;
    const int chunk = gw % 48;
    const int rest  = gw / 48;
    const int b     = rest & 3;
    const int seg   = rest >> 2;
    const int l0    = seg * CONV_SEG;
    const int c     = chunk * 128 + lane * 4;
    const bool norm = (chunk < 32);

    float4 w0 = *(const float4*)&conv_w[(c + 0) * 4];
    float4 w1 = *(const float4*)&conv_w[(c + 1) * 4];
    float4 w2 = *(const float4*)&conv_w[(c + 2) * 4];
    float4 w3 = *(const float4*)&conv_w[(c + 3) * 4];
    float4 bias = *(const float4*)&conv_b[c];

    const float* qbase = qkvz + (size_t)(b * NL) * QKVZN + c;
    float4 h0, h1, h2;
    h0 = (l0 >= 3) ? *(const float4*)(qbase + (size_t)(l0 - 3) * QKVZN) : make_float4(0, 0, 0, 0);
    h1 = (l0 >= 2) ? *(const float4*)(qbase + (size_t)(l0 - 2) * QKVZN) : make_float4(0, 0, 0, 0);
    h2 = (l0 >= 1) ? *(const float4*)(qbase + (size_t)(l0 - 1) * QKVZN) : make_float4(0, 0, 0, 0);

    float* obase = x_out + (size_t)(b * NL) * CONVD + chunk * 128 + lane * 4;

    for (int i = 0; i < CONV_SEG; i++) {
        const int l = l0 + i;
        float4 cur = *(const float4*)(qbase + (size_t)l * QKVZN);
        float4 acc;
        acc.x = bias.x + w0.x * h0.x + w0.y * h1.x + w0.z * h2.x + w0.w * cur.x;
        acc.y = bias.y + w1.x * h0.y + w1.y * h1.y + w1.z * h2.y + w1.w * cur.y;
        acc.z = bias.z + w2.x * h0.z + w2.y * h1.z + w2.z * h2.z + w2.w * cur.z;
        acc.w = bias.w + w3.x * h0.w + w3.y * h1.w + w3.z * h2.w + w3.w * cur.w;
        if (norm) {
            float ss = acc.x * acc.x + acc.y * acc.y + acc.z * acc.z + acc.w * acc.w;
#pragma unroll
            for (int off = 16; off; off >>= 1) ss += __shfl_xor_sync(0xffffffffu, ss, off);
            const float rn = rsqrtf(ss + 1e-6f);
            acc.x *= rn; acc.y *= rn; acc.z *= rn; acc.w *= rn;
        }
        *(float4*)(obase + (size_t)l * CONVD) = acc;
        h0 = h1; h1 = h2; h2 = cur;
    }
}

// ======= gated delta-rule scan: 2 independent halves per 512-thread block ====
// 64 blocks = (b,h); unit = tid>>8 selects d-half. Each unit is the R8 pipeline
// verbatim (own smem ring, own cp.async stream, own NAMED barrier) so the two
// dependency chains interleave on the SMSPs without coupling.
#define KQ_PAD 36
#define SCAN_D 8

__global__ void __launch_bounds__(512, 1) scan_kernel(const float* __restrict__ x,
                                                      const float* __restrict__ eg_in,
                                                      const float* __restrict__ bb,
                                                      float* __restrict__ o)
{
    const int bh   = blockIdx.x;       // 0..63
    const int b = bh >> 4, h = bh & 15;
    const int tid  = threadIdx.x;
    const int unit = tid >> 8;         // 0,1 = d-half
    const int utid = tid & 255;
    const int col = utid >> 2;
    const int sub = utid & 3;
    const int d   = unit * 64 + col;

    __shared__ __align__(16) float k_s[2][SCAN_D][4 * KQ_PAD];
    __shared__ __align__(16) float q_s[2][SCAN_D][4 * KQ_PAD];
    __shared__ __align__(16) float v_s[2][SCAN_D][64];
    __shared__ __align__(8)  float gb_s[2][SCAN_D][2];

    ull s2[16];
#pragma unroll
    for (int i = 0; i < 16; i++) s2[i] = 0ULL;

    // ---- per-thread cp.async source/dest (slot 0), strides per step/slot ----
    const float* src0;
    uint32_t dst0;
    if (utid < 128) {
        src0 = x + (size_t)b * NL * CONVD + KEYD + h * 128 + utid;           // k
        dst0 = smem_u32(&k_s[unit][0][(utid >> 5) * KQ_PAD + (utid & 31)]);
    } else {
        const int t = utid - 128;
        src0 = x + (size_t)b * NL * CONVD + h * 128 + t;                     // q
        dst0 = smem_u32(&q_s[unit][0][(t >> 5) * KQ_PAD + (t & 31)]);
    }
    const float* src1 = 0;
    uint32_t dst1 = 0;
    uint32_t d1slot = 0;
    int s1step = 0;
    if (utid < 64) {
        src1 = x + (size_t)b * NL * CONVD + 2 * KEYD + h * 128 + unit * 64 + utid;
        dst1 = smem_u32(&v_s[unit][0][utid]);  d1slot = 64 * 4;  s1step = CONVD;
    } else if (utid == 64) {
        src1 = eg_in + (size_t)(b * NL) * NH + h;
        dst1 = smem_u32(&gb_s[unit][0][0]);    d1slot = 8;       s1step = NH;
    } else if (utid == 65) {
        src1 = bb + (size_t)(b * NL) * NH + h;
        dst1 = smem_u32(&gb_s[unit][0][1]);    d1slot = 8;       s1step = NH;
    }
    const uint32_t d0slot = 4 * KQ_PAD * 4;   // 576 B
    const int barid = unit + 1;

    // prologue: issue steps 0 .. SCAN_D-2 (7 groups)
#pragma unroll
    for (int l = 0; l < SCAN_D - 1; l++) {
        const uint32_t s = (uint32_t)l;
        cp4(dst0 + s * d0slot, src0 + (size_t)l * CONVD);
        if (utid < 66) cp4(dst1 + s * d1slot, src1 + (size_t)l * s1step);
        cp_commit();
    }

    const float scale = 0.08838834764831845f;
    float* obase = o + (size_t)b * NL * VALD + h * 128 + d;

    for (int l = 0; l < NL; l++) {
        cp_wait<SCAN_D - 2>();
        bar_named(barid);

        // issue step l+D-1 into slot (l-1)%D
        const int lf = l + SCAN_D - 1;
        if (lf < NL) {
            const uint32_t s = (uint32_t)(lf & (SCAN_D - 1));
            cp4(dst0 + s * d0slot, src0 + (size_t)lf * CONVD);
            if (utid < 66) cp4(dst1 + s * d1slot, src1 + (size_t)lf * s1step);
        }
        cp_commit();

        // ---- compute on slot l%D ----
        const int cur = l & (SCAN_D - 1);
        const float eg   = gb_s[unit][cur][0];      // already exp(g)
        const float beta = gb_s[unit][cur][1];
        const float vv   = v_s[unit][cur][col];
        const ull eg2 = pack2(eg, eg);

        ulonglong2 kr[8], qr[8];
#pragma unroll
        for (int j = 0; j < 8; j++) {
            kr[j] = *(const ulonglong2*)&k_s[unit][cur][sub * KQ_PAD + j * 4];
            qr[j] = *(const ulonglong2*)&q_s[unit][cur][sub * KQ_PAD + j * 4];
        }

        // three parallel dots on S_old + hoisted eg*S_old
        ull a0 = 0, a1 = 0, a2 = 0, a3 = 0;   // k·S_old
        ull c0 = 0, c1 = 0;                   // q·S_old
        ull e0 = 0, e1 = 0;                   // q·k
        ull sm[16];
#pragma unroll
        for (int j = 0; j < 8; j++) {
            const ull sx = s2[2 * j], sy = s2[2 * j + 1];
            if ((j & 1) == 0) { a0 = fma2(kr[j].x, sx, a0); a1 = fma2(kr[j].y, sy, a1); }
            else              { a2 = fma2(kr[j].x, sx, a2); a3 = fma2(kr[j].y, sy, a3); }
            c0 = fma2(qr[j].x, sx, c0);
            c1 = fma2(qr[j].y, sy, c1);
            e0 = fma2(qr[j].x, kr[j].x, e0);
            e1 = fma2(qr[j].y, kr[j].y, e1);
            sm[2 * j]     = mul2(sx, eg2);
            sm[2 * j + 1] = mul2(sy, eg2);
        }
        float2 af = unpack2(add2(add2(a0, a1), add2(a2, a3)));
        float a_s = af.x + af.y;
        a_s += __shfl_xor_sync(0xffffffffu, a_s, 1);
        a_s += __shfl_xor_sync(0xffffffffu, a_s, 2);
        const float delta = (vv - eg * a_s) * beta;
        const ull d2v = pack2(delta, delta);

        // S_new = eg*S_old + k*delta
#pragma unroll
        for (int j = 0; j < 8; j++) {
            s2[2 * j]     = fma2(kr[j].x, d2v, sm[2 * j]);
            s2[2 * j + 1] = fma2(kr[j].y, d2v, sm[2 * j + 1]);
        }

        // output (off the loop-carried path)
        float2 cf = unpack2(add2(c0, c1));
        float c_s = cf.x + cf.y;
        float2 ef = unpack2(add2(e0, e1));
        float e_s = ef.x + ef.y;
        c_s += __shfl_xor_sync(0xffffffffu, c_s, 1);
        c_s += __shfl_xor_sync(0xffffffffu, c_s, 2);
        e_s += __shfl_xor_sync(0xffffffffu, e_s, 1);
        e_s += __shfl_xor_sync(0xffffffffu, e_s, 2);
        const float oo = eg * c_s + e_s * delta;
        if (sub == 0) obase[(size_t)l * VALD] = oo * scale;
    }
}

// ============ RMS norm + sigmoid(z) gate, fused bf16 hi/lo split =============
__global__ void __launch_bounds__(256) gate_norm_kernel(const float* __restrict__ qkvz,
                                                        const float* __restrict__ norm_w,
                                                        const float* __restrict__ o,
                                                        __nv_bfloat16* __restrict__ oh,
                                                        __nv_bfloat16* __restrict__ ol)
{
    const int gid  = blockIdx.x * 256 + threadIdx.x;
    const int wid  = gid >> 5;
    const int lane = gid & 31;
    const int bl = wid >> 4;
    const int h  = wid & 15;

    const size_t off = (size_t)bl * VALD + h * 128 + lane * 4;
    float4 ov = *(const float4*)(o + off);
    float ss = ov.x * ov.x + ov.y * ov.y + ov.z * ov.z + ov.w * ov.w;
#pragma unroll
    for (int sh = 16; sh; sh >>= 1) ss += __shfl_xor_sync(0xffffffffu, ss, sh);
    const float rs = rsqrtf(ss * (1.f / 128.f) + 1e-6f);

    const float4 z = *(const float4*)&qkvz[(size_t)bl * QKVZN + CONVD + h * 128 + lane * 4];
    const float4 w = *(const float4*)&norm_w[lane * 4];
    float g0 = ov.x * rs * w.x * (1.f / (1.f + expf(-z.x)));
    float g1 = ov.y * rs * w.y * (1.f / (1.f + expf(-z.y)));
    float g2 = ov.z * rs * w.z * (1.f / (1.f + expf(-z.z)));
    float g3 = ov.w * rs * w.w * (1.f / (1.f + expf(-z.w)));

    __nv_bfloat16 h0 = __float2bfloat16_rn(g0), h1 = __float2bfloat16_rn(g1);
    __nv_bfloat16 h2 = __float2bfloat16_rn(g2), h3 = __float2bfloat16_rn(g3);
    __nv_bfloat162* hp = (__nv_bfloat162*)(oh + off);
    __nv_bfloat162* lp = (__nv_bfloat162*)(ol + off);
    hp[0] = __nv_bfloat162(h0, h1); hp[1] = __nv_bfloat162(h2, h3);
    lp[0] = __nv_bfloat162(__float2bfloat16_rn(g0 - __bfloat162float(h0)),
                           __float2bfloat16_rn(g1 - __bfloat162float(h1)));
    lp[1] = __nv_bfloat162(__float2bfloat16_rn(g2 - __bfloat162float(h2)),
                           __float2bfloat16_rn(g3 - __bfloat162float(h3)));
}

// ====================================================================
extern "C" void kernel_launch(void* const* d_in, const int* in_sizes, int n_in,
                              void* d_out, int out_size)
{
    const float* hidden  = (const float*)d_in[0];
    const float* W_qkvz  = (const float*)d_in[1];
    const float* W_ba    = (const float*)d_in[2];
    const float* conv_w  = (const float*)d_in[3];
    const float* conv_b  = (const float*)d_in[4];
    const float* A_log   = (const float*)d_in[5];
    const float* dt_bias = (const float*)d_in[6];
    const float* norm_w  = (const float*)d_in[7];
    const float* W_out   = (const float*)d_in[8];
    float* out = (float*)d_out;

    float *qkvz, *xbuf, *egbuf, *betabuf, *obuf;
    __nv_bfloat16 *hh, *hl, *wqh, *wql, *woh, *wol, *oh, *ol;
    cudaGetSymbolAddress((void**)&qkvz,    g_qkvz);
    cudaGetSymbolAddress((void**)&xbuf,    g_x);
    cudaGetSymbolAddress((void**)&egbuf,   g_g);
    cudaGetSymbolAddress((void**)&betabuf, g_beta);
    cudaGetSymbolAddress((void**)&obuf,    g_o);
    cudaGetSymbolAddress((void**)&hh,  g_hh);
    cudaGetSymbolAddress((void**)&hl,  g_hl);
    cudaGetSymbolAddress((void**)&wqh, g_wqh);
    cudaGetSymbolAddress((void**)&wql, g_wql);
    cudaGetSymbolAddress((void**)&woh, g_woh);
    cudaGetSymbolAddress((void**)&wol, g_wol);
    cudaGetSymbolAddress((void**)&oh,  g_oh);
    cudaGetSymbolAddress((void**)&ol,  g_ol);

    cudaFuncSetAttribute(mma_gemm, cudaFuncAttributeMaxDynamicSharedMemorySize, GEMM_SMEM);

    // #1  split hidden -> bf16 hi/lo
    split_kernel<<<(ML * HID / 4 + 255) / 256, 256>>>(hidden, hh, hl, ML * HID / 4);
    // #2  transpose+split W_qkvz
    tsplit_kernel<<<dim3(QKVZN / 32, HID / 32), dim3(32, 8)>>>(W_qkvz, wqh, wql, HID, QKVZN);
    // #3  qkvz = hidden @ W_qkvz   [4096, 8192]
    mma_gemm<<<dim3(QKVZN / BN, ML / BM), 256, GEMM_SMEM>>>(hh, hl, wqh, wql, qkvz, HID, QKVZN);
    // #4  ba GEMM + fused exp(g)/beta
    ba_gb_kernel<<<ML / 8, 256>>>(hidden, W_ba, A_log, dt_bias, egbuf, betabuf);
    // #5  depthwise conv + l2norm
    conv_kernel<<<CONV_BLOCKS, 256>>>(qkvz, conv_w, conv_b, xbuf);
    // #6  gated delta scan (two independent halves per 512-thread block)
    scan_kernel<<<64, 512>>>(xbuf, egbuf, betabuf, obuf);
    // #7  RMS norm + sigmoid(z) gate + bf16 split (fused)
    gate_norm_kernel<<<(ML * NH * 32) / 256, 256>>>(qkvz, norm_w, obuf, oh, ol);
    // #8  transpose+split W_out
    tsplit_kernel<<<dim3(HID / 32, VALD / 32), dim3(32, 8)>>>(W_out, woh, wol, VALD, HID);
    // #9  out = o @ W_out          [4096, 2048]
    mma_gemm<<<dim3(HID / BN, ML / BM), 256, GEMM_SMEM>>>(oh, ol, woh, wol, out, VALD, HID);
}

// round 17
// speedup vs baseline: 1.2275x; 1.2275x over previous
#include <cuda_runtime.h>
#include <cuda_bf16.h>
#include <math.h>
#include <stdint.h>

// ---------------- problem constants ----------------
#define NB    4
#define NL    1024
#define HID   2048
#define NH    16
#define DK    128
#define DV    128
#define KEYD  2048          // H*DK
#define VALD  2048          // H*DV
#define CONVD 6144          // 2*KEYD + VALD
#define QKVZN 8192          // 2*KEYD + 2*VALD
#define ML    4096          // B*L

typedef unsigned long long ull;

// ---------------- device scratch (static, no allocs) ----------------
__device__ float g_qkvz[(size_t)ML * QKVZN];   // 128 MiB
__device__ float g_x[(size_t)ML * CONVD];
__device__ float g_g[ML * NH];                 // holds exp(g)
__device__ float g_beta[ML * NH];
__device__ float g_o[(size_t)ML * VALD];

// bf16 hi/lo split operands
__device__ __nv_bfloat16 g_hh[(size_t)ML * HID];
__device__ __nv_bfloat16 g_hl[(size_t)ML * HID];
__device__ __nv_bfloat16 g_wqh[(size_t)QKVZN * HID];   // W_qkvz^T  [N,K]
__device__ __nv_bfloat16 g_wql[(size_t)QKVZN * HID];
__device__ __nv_bfloat16 g_woh[(size_t)HID * VALD];    // W_out^T   [N,K]
__device__ __nv_bfloat16 g_wol[(size_t)HID * VALD];
__device__ __nv_bfloat16 g_oh[(size_t)ML * VALD];
__device__ __nv_bfloat16 g_ol[(size_t)ML * VALD];

// ==================== PTX helpers (base compute_103 safe) ====================
__device__ __forceinline__ uint32_t smem_u32(const void* p) {
    uint32_t a;
    asm("{ .reg .u64 t; cvta.to.shared.u64 t, %1; cvt.u32.u64 %0, t; }" : "=r"(a) : "l"(p));
    return a;
}
__device__ __forceinline__ void cp16(uint32_t dst, const void* src) {
    asm volatile("cp.async.cg.shared.global [%0], [%1], 16;" :: "r"(dst), "l"(src));
}
__device__ __forceinline__ void cp4(uint32_t dst, const void* src) {
    asm volatile("cp.async.ca.shared.global [%0], [%1], 4;" :: "r"(dst), "l"(src));
}
__device__ __forceinline__ void cp_commit() {
    asm volatile("cp.async.commit_group;" ::: "memory");
}
template<int N>
__device__ __forceinline__ void cp_wait() {
    asm volatile("cp.async.wait_group %0;" :: "n"(N) : "memory");
}
__device__ __forceinline__ void ldsm4(uint32_t* r, uint32_t addr) {
    asm volatile("ldmatrix.sync.aligned.m8n8.x4.shared.b16 {%0,%1,%2,%3}, [%4];"
                 : "=r"(r[0]), "=r"(r[1]), "=r"(r[2]), "=r"(r[3]) : "r"(addr));
}
__device__ __forceinline__ void mma16816(float* c, const uint32_t* a, const uint32_t* b) {
    asm volatile("mma.sync.aligned.m16n8k16.row.col.f32.bf16.bf16.f32 "
                 "{%0,%1,%2,%3}, {%4,%5,%6,%7}, {%8,%9}, {%0,%1,%2,%3};"
                 : "+f"(c[0]), "+f"(c[1]), "+f"(c[2]), "+f"(c[3])
                 : "r"(a[0]), "r"(a[1]), "r"(a[2]), "r"(a[3]), "r"(b[0]), "r"(b[1]));
}
__device__ __forceinline__ uint32_t sw128(uint32_t off) {
    return off ^ ((off >> 3) & 0x70);
}
// packed f32x2 (sm_100+ base ISA)
__device__ __forceinline__ ull pack2(float x, float y) {
    ull r; asm("mov.b64 %0, {%1, %2};" : "=l"(r) : "f"(x), "f"(y)); return r;
}
__device__ __forceinline__ float2 unpack2(ull v) {
    float2 f; asm("mov.b64 {%0, %1}, %2;" : "=f"(f.x), "=f"(f.y) : "l"(v)); return f;
}
__device__ __forceinline__ ull fma2(ull a, ull b, ull c) {
    ull d; asm("fma.rn.f32x2 %0, %1, %2, %3;" : "=l"(d) : "l"(a), "l"(b), "l"(c)); return d;
}
__device__ __forceinline__ ull mul2(ull a, ull b) {
    ull d; asm("mul.rn.f32x2 %0, %1, %2;" : "=l"(d) : "l"(a), "l"(b)); return d;
}
__device__ __forceinline__ ull add2(ull a, ull b) {
    ull d; asm("add.rn.f32x2 %0, %1, %2;" : "=l"(d) : "l"(a), "l"(b)); return d;
}

// ==================== mma.sync bf16 GEMM (3-product hi/lo split) =============
#define BM 128
#define BN 64
#define BKC 64
#define A_TILE_B 16384                    // 128x64 bf16
#define B_TILE_B 8192                     // 64x64 bf16
#define STAGE_B (2 * A_TILE_B + 2 * B_TILE_B)   // 48 KiB
#define GEMM_SMEM (2 * STAGE_B)                 // 96 KiB

__device__ __forceinline__ void gemm_load_chunk(
    const __nv_bfloat16* Ah, const __nv_bfloat16* Al,
    const __nv_bfloat16* Bh, const __nv_bfloat16* Bl,
    int Kdim, int k0, uint32_t sbuf, int tid)
{
#pragma unroll
    for (int it = 0; it < 4; it++) {          // A: 128 rows x 8 x16B
        const int u   = it * 256 + tid;
        const int row = u >> 3;
        const int cb  = (u & 7) << 4;
        const uint32_t so = sw128((uint32_t)(row * 128 + cb));
        const size_t go = (size_t)row * Kdim + k0;
        cp16(sbuf + 0 * A_TILE_B + so, (const char*)(Ah + go) + cb);
        cp16(sbuf + 1 * A_TILE_B + so, (const char*)(Al + go) + cb);
    }
#pragma unroll
    for (int it = 0; it < 2; it++) {          // B: 64 rows x 8 x16B
        const int u   = it * 256 + tid;
        const int row = u >> 3;
        const int cb  = (u & 7) << 4;
        const uint32_t so = sw128((uint32_t)(row * 128 + cb));
        const size_t go = (size_t)row * Kdim + k0;
        cp16(sbuf + 2 * A_TILE_B + so,             (const char*)(Bh + go) + cb);
        cp16(sbuf + 2 * A_TILE_B + B_TILE_B + so,  (const char*)(Bl + go) + cb);
    }
}

__global__ void __launch_bounds__(256, 2) mma_gemm(
    const __nv_bfloat16* __restrict__ Ah, const __nv_bfloat16* __restrict__ Al,
    const __nv_bfloat16* __restrict__ Bh, const __nv_bfloat16* __restrict__ Bl,
    float* __restrict__ C, int Kdim, int Nout)
{
    extern __shared__ __align__(1024) char smem[];
    const uint32_t sbase = smem_u32(smem);
    const int tid  = threadIdx.x;
    const int wid  = tid >> 5;
    const int lane = tid & 31;
    const int wm = wid >> 2;          // 0..1
    const int wn = wid & 3;           // 0..3
    const int m0 = blockIdx.y * BM;
    const int n0 = blockIdx.x * BN;

    const __nv_bfloat16* Ahb = Ah + (size_t)m0 * Kdim;
    const __nv_bfloat16* Alb = Al + (size_t)m0 * Kdim;
    const __nv_bfloat16* Bhb = Bh + (size_t)n0 * Kdim;
    const __nv_bfloat16* Blb = Bl + (size_t)n0 * Kdim;

    float acc[4][2][4];
#pragma unroll
    for (int i = 0; i < 4; i++)
#pragma unroll
        for (int j = 0; j < 2; j++)
#pragma unroll
            for (int r = 0; r < 4; r++) acc[i][j][r] = 0.f;

    const uint32_t a_off0 = (uint32_t)((wm * 64 + (lane & 15)) * 128 + ((lane >> 4) << 4));
    const uint32_t b_off0 = (uint32_t)((wn * 16 + (lane & 7) + ((lane >> 4) << 3)) * 128
                                       + (((lane >> 3) & 1) << 4));

    gemm_load_chunk(Ahb, Alb, Bhb, Blb, Kdim, 0, sbase, tid);
    cp_commit();

    const int nchunks = Kdim / BKC;
    for (int c = 0; c < nchunks; c++) {
        const uint32_t buf = sbase + (uint32_t)(c & 1) * STAGE_B;
        cp_wait<0>();
        __syncthreads();
        if (c + 1 < nchunks) {
            gemm_load_chunk(Ahb, Alb, Bhb, Blb, Kdim, (c + 1) * BKC,
                            sbase + (uint32_t)((c + 1) & 1) * STAGE_B, tid);
            cp_commit();
        }

        const uint32_t aHi = buf, aLo = buf + A_TILE_B;
        const uint32_t bHi = buf + 2 * A_TILE_B, bLo = bHi + B_TILE_B;
#pragma unroll
        for (int k16 = 0; k16 < 4; k16++) {
            uint32_t ah[4][4], al[4][4], bh[4], bl[4];
#pragma unroll
            for (int mt = 0; mt < 4; mt++) {
                const uint32_t off = sw128(a_off0 + (uint32_t)(mt * 16 * 128 + k16 * 32));
                ldsm4(ah[mt], aHi + off);
                ldsm4(al[mt], aLo + off);
            }
            {
                const uint32_t off = sw128(b_off0 + (uint32_t)(k16 * 32));
                ldsm4(bh, bHi + off);
                ldsm4(bl, bLo + off);
            }
#pragma unroll
            for (int mt = 0; mt < 4; mt++) {
#pragma unroll
                for (int nt = 0; nt < 2; nt++) {
                    const uint32_t* bhp = &bh[nt * 2];
                    const uint32_t* blp = &bl[nt * 2];
                    mma16816(acc[mt][nt], ah[mt], bhp);
                    mma16816(acc[mt][nt], ah[mt], blp);
                    mma16816(acc[mt][nt], al[mt], bhp);
                }
            }
        }
        __syncthreads();
    }

    const int rbase = m0 + wm * 64 + (lane >> 2);
    const int cbase = n0 + wn * 16 + (lane & 3) * 2;
#pragma unroll
    for (int mt = 0; mt < 4; mt++) {
#pragma unroll
        for (int nt = 0; nt < 2; nt++) {
            float* p0 = C + (size_t)(rbase + mt * 16) * Nout + cbase + nt * 8;
            float* p1 = p0 + 8 * Nout;
            *(float2*)p0 = make_float2(acc[mt][nt][0], acc[mt][nt][1]);
            *(float2*)p1 = make_float2(acc[mt][nt][2], acc[mt][nt][3]);
        }
    }
}

// ==================== fp32 -> bf16 hi/lo split ====================
__global__ void __launch_bounds__(256) split_kernel(const float* __restrict__ s,
                                                    __nv_bfloat16* __restrict__ hi,
                                                    __nv_bfloat16* __restrict__ lo,
                                                    int n4)
{
    const int i = blockIdx.x * 256 + threadIdx.x;
    if (i >= n4) return;
    float4 v = ((const float4*)s)[i];
    __nv_bfloat16 h0 = __float2bfloat16_rn(v.x);
    __nv_bfloat16 h1 = __float2bfloat16_rn(v.y);
    __nv_bfloat16 h2 = __float2bfloat16_rn(v.z);
    __nv_bfloat16 h3 = __float2bfloat16_rn(v.w);
    __nv_bfloat16 l0 = __float2bfloat16_rn(v.x - __bfloat162float(h0));
    __nv_bfloat16 l1 = __float2bfloat16_rn(v.y - __bfloat162float(h1));
    __nv_bfloat16 l2 = __float2bfloat16_rn(v.z - __bfloat162float(h2));
    __nv_bfloat16 l3 = __float2bfloat16_rn(v.w - __bfloat162float(h3));
    __nv_bfloat162* hp = (__nv_bfloat162*)(hi + (size_t)i * 4);
    __nv_bfloat162* lp = (__nv_bfloat162*)(lo + (size_t)i * 4);
    hp[0] = __nv_bfloat162(h0, h1); hp[1] = __nv_bfloat162(h2, h3);
    lp[0] = __nv_bfloat162(l0, l1); lp[1] = __nv_bfloat162(l2, l3);
}

// transpose + split: src[K,N] f32 -> hi/lo [N,K] bf16
__global__ void __launch_bounds__(256) tsplit_kernel(const float* __restrict__ src,
                                                     __nv_bfloat16* __restrict__ hi,
                                                     __nv_bfloat16* __restrict__ lo,
                                                     int K, int N)
{
    __shared__ float t[32][33];
    const int n0 = blockIdx.x * 32;
    const int k0 = blockIdx.y * 32;
    for (int j = threadIdx.y; j < 32; j += 8)
        t[j][threadIdx.x] = src[(size_t)(k0 + j) * N + n0 + threadIdx.x];
    __syncthreads();
    for (int j = threadIdx.y; j < 32; j += 8) {
        const float x = t[threadIdx.x][j];
        const __nv_bfloat16 h = __float2bfloat16_rn(x);
        const size_t oi = (size_t)(n0 + j) * K + k0 + threadIdx.x;
        hi[oi] = h;
        lo[oi] = __float2bfloat16_rn(x - __bfloat162float(h));
    }
}

// ===== small GEMM: ba[4096,32] + exp(g)/beta, 2-way K-split for occupancy ====
// 1024 blocks x 8 warps: warp w -> row blk*4 + (w>>1), K-half (w&1).
// Partials combined through smem; epilogue pairs b/a via shfl-16.
__global__ void __launch_bounds__(256) ba_gb_kernel(const float* __restrict__ A,
                                                    const float* __restrict__ Bm,
                                                    const float* __restrict__ A_log,
                                                    const float* __restrict__ dt_bias,
                                                    float* __restrict__ eg_out,
                                                    float* __restrict__ beta_out)
{
    __shared__ float part[8][32];
    const int wid  = threadIdx.x >> 5;
    const int lane = threadIdx.x & 31;
    const int row  = blockIdx.x * 4 + (wid >> 1);
    const int kh   = wid & 1;
    const float* a = A + (size_t)row * HID + kh * (HID / 2);
    const float* B = Bm + kh * (HID / 2) * 32;

    float acc = 0.f;
#pragma unroll 4
    for (int k = 0; k < HID / 2; k += 4) {
        float4 av = *(const float4*)&a[k];
        acc += av.x * B[(k + 0) * 32 + lane];
        acc += av.y * B[(k + 1) * 32 + lane];
        acc += av.z * B[(k + 2) * 32 + lane];
        acc += av.w * B[(k + 3) * 32 + lane];
    }
    part[wid][lane] = acc;
    __syncthreads();
    if (kh == 0) {
        acc += part[wid + 1][lane];
        const float other = __shfl_xor_sync(0xffffffffu, acc, 16);
        if (lane < 16) {
            const int h = lane;
            const float s = other + dt_bias[h];
            const float sp = (s > 20.f) ? s : log1pf(expf(s));
            eg_out[row * NH + h]   = expf(-expf(A_log[h]) * sp);
            beta_out[row * NH + h] = 1.f / (1.f + expf(-acc));
        }
    }
}

// ============ conv1d (rolling window, 1 warp per 128-col chunk) + l2norm =====
#define CONV_LSPLIT 16
#define CONV_SEG (NL / CONV_LSPLIT)          // 64
#define CONV_WARPS (NB * 48 * CONV_LSPLIT)   // 3072 warps
#define CONV_BLOCKS (CONV_WARPS / 8)         // 384

__global__ void __launch_bounds__(256) conv_kernel(const float* __restrict__ qkvz,
                                                   const float* __restrict__ conv_w,
                                                   const float* __restrict__ conv_b,
                                                   float* __restrict__ x_out)
{
    const int gw   = blockIdx.x * 8 + (threadIdx.x >> 5);
    const int lane = threadIdx.x & 31;
    const int chunk = gw % 48;
    const int rest  = gw / 48;
    const int b     = rest & 3;
    const int seg   = rest >> 2;
    const int l0    = seg * CONV_SEG;
    const int c     = chunk * 128 + lane * 4;
    const bool norm = (chunk < 32);

    float4 w0 = *(const float4*)&conv_w[(c + 0) * 4];
    float4 w1 = *(const float4*)&conv_w[(c + 1) * 4];
    float4 w2 = *(const float4*)&conv_w[(c + 2) * 4];
    float4 w3 = *(const float4*)&conv_w[(c + 3) * 4];
    float4 bias = *(const float4*)&conv_b[c];

    const float* qbase = qkvz + (size_t)(b * NL) * QKVZN + c;
    float4 h0, h1, h2;
    h0 = (l0 >= 3) ? *(const float4*)(qbase + (size_t)(l0 - 3) * QKVZN) : make_float4(0, 0, 0, 0);
    h1 = (l0 >= 2) ? *(const float4*)(qbase + (size_t)(l0 - 2) * QKVZN) : make_float4(0, 0, 0, 0);
    h2 = (l0 >= 1) ? *(const float4*)(qbase + (size_t)(l0 - 1) * QKVZN) : make_float4(0, 0, 0, 0);

    float* obase = x_out + (size_t)(b * NL) * CONVD + chunk * 128 + lane * 4;

    for (int i = 0; i < CONV_SEG; i++) {
        const int l = l0 + i;
        float4 cur = *(const float4*)(qbase + (size_t)l * QKVZN);
        float4 acc;
        acc.x = bias.x + w0.x * h0.x + w0.y * h1.x + w0.z * h2.x + w0.w * cur.x;
        acc.y = bias.y + w1.x * h0.y + w1.y * h1.y + w1.z * h2.y + w1.w * cur.y;
        acc.z = bias.z + w2.x * h0.z + w2.y * h1.z + w2.z * h2.z + w2.w * cur.z;
        acc.w = bias.w + w3.x * h0.w + w3.y * h1.w + w3.z * h2.w + w3.w * cur.w;
        if (norm) {
            float ss = acc.x * acc.x + acc.y * acc.y + acc.z * acc.z + acc.w * acc.w;
#pragma unroll
            for (int off = 16; off; off >>= 1) ss += __shfl_xor_sync(0xffffffffu, ss, off);
            const float rn = rsqrtf(ss + 1e-6f);
            acc.x *= rn; acc.y *= rn; acc.z *= rn; acc.w *= rn;
        }
        *(float4*)(obase + (size_t)l * CONVD) = acc;
        h0 = h1; h1 = h2; h2 = cur;
    }
}

// ======= gated delta-rule scan: cp.async ring (depth 8), packed f32x2 ========
// R8/R12-best configuration (128 blocks, col=tid>>2, sub=tid&3, KQ_PAD=36).
// o = eg*(q·S_old) + (q·k)*delta ; S_new = eg*S_old + k*delta.
#define KQ_PAD 36
#define SCAN_D 8

__global__ void __launch_bounds__(256) scan_kernel(const float* __restrict__ x,
                                                   const float* __restrict__ eg_in,
                                                   const float* __restrict__ bb,
                                                   float* __restrict__ o)
{
    const int blk  = blockIdx.x;
    const int bh   = blk >> 1;
    const int half = blk & 1;
    const int b = bh >> 4, h = bh & 15;
    const int tid = threadIdx.x;
    const int col = tid >> 2;
    const int sub = tid & 3;
    const int d   = half * 64 + col;

    __shared__ __align__(16) float k_s[SCAN_D][4 * KQ_PAD];
    __shared__ __align__(16) float q_s[SCAN_D][4 * KQ_PAD];
    __shared__ __align__(16) float v_s[SCAN_D][64];
    __shared__ __align__(8)  float gb_s[SCAN_D][2];

    ull s2[16];
#pragma unroll
    for (int i = 0; i < 16; i++) s2[i] = 0ULL;

    const float* src0;
    uint32_t dst0;
    if (tid < 128) {
        src0 = x + (size_t)b * NL * CONVD + KEYD + h * 128 + tid;           // k
        dst0 = smem_u32(&k_s[0][(tid >> 5) * KQ_PAD + (tid & 31)]);
    } else {
        const int t = tid - 128;
        src0 = x + (size_t)b * NL * CONVD + h * 128 + t;                    // q
        dst0 = smem_u32(&q_s[0][(t >> 5) * KQ_PAD + (t & 31)]);
    }
    const float* src1 = 0;
    uint32_t dst1 = 0;
    uint32_t d1slot = 0;
    int s1step = 0;
    if (tid < 64) {
        src1 = x + (size_t)b * NL * CONVD + 2 * KEYD + h * 128 + half * 64 + tid;
        dst1 = smem_u32(&v_s[0][tid]);  d1slot = 64 * 4;  s1step = CONVD;
    } else if (tid == 64) {
        src1 = eg_in + (size_t)(b * NL) * NH + h;
        dst1 = smem_u32(&gb_s[0][0]);   d1slot = 8;       s1step = NH;
    } else if (tid == 65) {
        src1 = bb + (size_t)(b * NL) * NH + h;
        dst1 = smem_u32(&gb_s[0][1]);   d1slot = 8;       s1step = NH;
    }
    const uint32_t d0slot = 4 * KQ_PAD * 4;   // 576 B

#pragma unroll
    for (int l = 0; l < SCAN_D - 1; l++) {
        const uint32_t s = (uint32_t)l;
        cp4(dst0 + s * d0slot, src0 + (size_t)l * CONVD);
        if (tid < 66) cp4(dst1 + s * d1slot, src1 + (size_t)l * s1step);
        cp_commit();
    }

    const float scale = 0.08838834764831845f;
    float* obase = o + (size_t)b * NL * VALD + h * 128 + d;

    for (int l = 0; l < NL; l++) {
        cp_wait<SCAN_D - 2>();
        __syncthreads();

        const int lf = l + SCAN_D - 1;
        if (lf < NL) {
            const uint32_t s = (uint32_t)(lf & (SCAN_D - 1));
            cp4(dst0 + s * d0slot, src0 + (size_t)lf * CONVD);
            if (tid < 66) cp4(dst1 + s * d1slot, src1 + (size_t)lf * s1step);
        }
        cp_commit();

        const int cur = l & (SCAN_D - 1);
        const float eg   = gb_s[cur][0];      // already exp(g)
        const float beta = gb_s[cur][1];
        const float vv   = v_s[cur][col];
        const ull eg2 = pack2(eg, eg);

        ulonglong2 kr[8], qr[8];
#pragma unroll
        for (int j = 0; j < 8; j++) {
            kr[j] = *(const ulonglong2*)&k_s[cur][sub * KQ_PAD + j * 4];
            qr[j] = *(const ulonglong2*)&q_s[cur][sub * KQ_PAD + j * 4];
        }

        ull a0 = 0, a1 = 0, a2 = 0, a3 = 0;   // k·S_old
        ull c0 = 0, c1 = 0;                   // q·S_old
        ull e0 = 0, e1 = 0;                   // q·k
        ull sm[16];
#pragma unroll
        for (int j = 0; j < 8; j++) {
            const ull sx = s2[2 * j], sy = s2[2 * j + 1];
            if ((j & 1) == 0) { a0 = fma2(kr[j].x, sx, a0); a1 = fma2(kr[j].y, sy, a1); }
            else              { a2 = fma2(kr[j].x, sx, a2); a3 = fma2(kr[j].y, sy, a3); }
            c0 = fma2(qr[j].x, sx, c0);
            c1 = fma2(qr[j].y, sy, c1);
            e0 = fma2(qr[j].x, kr[j].x, e0);
            e1 = fma2(qr[j].y, kr[j].y, e1);
            sm[2 * j]     = mul2(sx, eg2);
            sm[2 * j + 1] = mul2(sy, eg2);
        }
        float2 af = unpack2(add2(add2(a0, a1), add2(a2, a3)));
        float a_s = af.x + af.y;
        a_s += __shfl_xor_sync(0xffffffffu, a_s, 1);
        a_s += __shfl_xor_sync(0xffffffffu, a_s, 2);
        const float delta = (vv - eg * a_s) * beta;
        const ull d2v = pack2(delta, delta);

#pragma unroll
        for (int j = 0; j < 8; j++) {
            s2[2 * j]     = fma2(kr[j].x, d2v, sm[2 * j]);
            s2[2 * j + 1] = fma2(kr[j].y, d2v, sm[2 * j + 1]);
        }

        float2 cf = unpack2(add2(c0, c1));
        float c_s = cf.x + cf.y;
        float2 ef = unpack2(add2(e0, e1));
        float e_s = ef.x + ef.y;
        c_s += __shfl_xor_sync(0xffffffffu, c_s, 1);
        c_s += __shfl_xor_sync(0xffffffffu, c_s, 2);
        e_s += __shfl_xor_sync(0xffffffffu, e_s, 1);
        e_s += __shfl_xor_sync(0xffffffffu, e_s, 2);
        const float oo = eg * c_s + e_s * delta;
        if (sub == 0) obase[(size_t)l * VALD] = oo * scale;
    }
}

// ============ RMS norm + sigmoid(z) gate, fused bf16 hi/lo split =============
__global__ void __launch_bounds__(256) gate_norm_kernel(const float* __restrict__ qkvz,
                                                        const float* __restrict__ norm_w,
                                                        const float* __restrict__ o,
                                                        __nv_bfloat16* __restrict__ oh,
                                                        __nv_bfloat16* __restrict__ ol)
{
    const int gid  = blockIdx.x * 256 + threadIdx.x;
    const int wid  = gid >> 5;
    const int lane = gid & 31;
    const int bl = wid >> 4;
    const int h  = wid & 15;

    const size_t off = (size_t)bl * VALD + h * 128 + lane * 4;
    float4 ov = *(const float4*)(o + off);
    float ss = ov.x * ov.x + ov.y * ov.y + ov.z * ov.z + ov.w * ov.w;
#pragma unroll
    for (int sh = 16; sh; sh >>= 1) ss += __shfl_xor_sync(0xffffffffu, ss, sh);
    const float rs = rsqrtf(ss * (1.f / 128.f) + 1e-6f);

    const float4 z = *(const float4*)&qkvz[(size_t)bl * QKVZN + CONVD + h * 128 + lane * 4];
    const float4 w = *(const float4*)&norm_w[lane * 4];
    float g0 = ov.x * rs * w.x * (1.f / (1.f + expf(-z.x)));
    float g1 = ov.y * rs * w.y * (1.f / (1.f + expf(-z.y)));
    float g2 = ov.z * rs * w.z * (1.f / (1.f + expf(-z.z)));
    float g3 = ov.w * rs * w.w * (1.f / (1.f + expf(-z.w)));

    __nv_bfloat16 h0 = __float2bfloat16_rn(g0), h1 = __float2bfloat16_rn(g1);
    __nv_bfloat16 h2 = __float2bfloat16_rn(g2), h3 = __float2bfloat16_rn(g3);
    __nv_bfloat162* hp = (__nv_bfloat162*)(oh + off);
    __nv_bfloat162* lp = (__nv_bfloat162*)(ol + off);
    hp[0] = __nv_bfloat162(h0, h1); hp[1] = __nv_bfloat162(h2, h3);
    lp[0] = __nv_bfloat162(__float2bfloat16_rn(g0 - __bfloat162float(h0)),
                           __float2bfloat16_rn(g1 - __bfloat162float(h1)));
    lp[1] = __nv_bfloat162(__float2bfloat16_rn(g2 - __bfloat162float(h2)),
                           __float2bfloat16_rn(g3 - __bfloat162float(h3)));
}

// ====================================================================
extern "C" void kernel_launch(void* const* d_in, const int* in_sizes, int n_in,
                              void* d_out, int out_size)
{
    const float* hidden  = (const float*)d_in[0];
    const float* W_qkvz  = (const float*)d_in[1];
    const float* W_ba    = (const float*)d_in[2];
    const float* conv_w  = (const float*)d_in[3];
    const float* conv_b  = (const float*)d_in[4];
    const float* A_log   = (const float*)d_in[5];
    const float* dt_bias = (const float*)d_in[6];
    const float* norm_w  = (const float*)d_in[7];
    const float* W_out   = (const float*)d_in[8];
    float* out = (float*)d_out;

    float *qkvz, *xbuf, *egbuf, *betabuf, *obuf;
    __nv_bfloat16 *hh, *hl, *wqh, *wql, *woh, *wol, *oh, *ol;
    cudaGetSymbolAddress((void**)&qkvz,    g_qkvz);
    cudaGetSymbolAddress((void**)&xbuf,    g_x);
    cudaGetSymbolAddress((void**)&egbuf,   g_g);
    cudaGetSymbolAddress((void**)&betabuf, g_beta);
    cudaGetSymbolAddress((void**)&obuf,    g_o);
    cudaGetSymbolAddress((void**)&hh,  g_hh);
    cudaGetSymbolAddress((void**)&hl,  g_hl);
    cudaGetSymbolAddress((void**)&wqh, g_wqh);
    cudaGetSymbolAddress((void**)&wql, g_wql);
    cudaGetSymbolAddress((void**)&woh, g_woh);
    cudaGetSymbolAddress((void**)&wol, g_wol);
    cudaGetSymbolAddress((void**)&oh,  g_oh);
    cudaGetSymbolAddress((void**)&ol,  g_ol);

    cudaFuncSetAttribute(mma_gemm, cudaFuncAttributeMaxDynamicSharedMemorySize, GEMM_SMEM);

    // #1  split hidden -> bf16 hi/lo
    split_kernel<<<(ML * HID / 4 + 255) / 256, 256>>>(hidden, hh, hl, ML * HID / 4);
    // #2  transpose+split W_qkvz
    tsplit_kernel<<<dim3(QKVZN / 32, HID / 32), dim3(32, 8)>>>(W_qkvz, wqh, wql, HID, QKVZN);
    // #3  qkvz = hidden @ W_qkvz   [4096, 8192]
    mma_gemm<<<dim3(QKVZN / BN, ML / BM), 256, GEMM_SMEM>>>(hh, hl, wqh, wql, qkvz, HID, QKVZN);
    // #4  ba GEMM + fused exp(g)/beta (2-way K-split)
    ba_gb_kernel<<<ML / 4, 256>>>(hidden, W_ba, A_log, dt_bias, egbuf, betabuf);
    // #5  depthwise conv + l2norm
    conv_kernel<<<CONV_BLOCKS, 256>>>(qkvz, conv_w, conv_b, xbuf);
    // #6  gated delta scan (R12-best form)
    scan_kernel<<<128, 256>>>(xbuf, egbuf, betabuf, obuf);
    // #7  RMS norm + sigmoid(z) gate + bf16 split (fused)
    gate_norm_kernel<<<(ML * NH * 32) / 256, 256>>>(qkvz, norm_w, obuf, oh, ol);
    // #8  transpose+split W_out
    tsplit_kernel<<<dim3(HID / 32, VALD / 32), dim3(32, 8)>>>(W_out, woh, wol, VALD, HID);
    // #9  out = o @ W_out          [4096, 2048]
    mma_gemm<<<dim3(HID / BN, ML / BM), 256, GEMM_SMEM>>>(oh, ol, woh, wol, out, VALD, HID);
}